// round 3
// baseline (speedup 1.0000x reference)
#include <cuda_runtime.h>

#define CB 4
#define CN 1024
#define CD 512
#define CH 8
#define CDH 64
#define CTC 512
#define CAB 16

// ---------------- scratch (device globals: no allocations allowed) ----------
__device__ float g_film[CB * 2 * CD];                 // [B][2D]
__device__ float g_xn[CB * CN * CD];                  // [B,N,D]
__device__ float g_q[CB * CH * CN * CDH];             // [B,H,N,DH] (pre-scaled)
__device__ float g_k[CB * CH * CN * CDH];
__device__ float g_v[CB * CH * CN * CDH];
__device__ float g_o[CB * CN * CH * CDH];             // [B,N,H*DH]
__device__ float g_bias[CB * CH * CN * CN];           // [B,H,N,N]  (128 MB)

// ---------------- kernel 1: FiLM params t = silu(time) @ Wt^T + bt ----------
__global__ void __launch_bounds__(256) film_kernel(
    const float* __restrict__ timep, const float* __restrict__ Wt,
    const float* __restrict__ bt) {
  const int b = blockIdx.y;
  __shared__ float st[CTC];
  const int tid = threadIdx.x;
  for (int t = tid; t < CTC; t += 256) {
    float v = timep[b * CTC + t];
    st[t] = v / (1.f + __expf(-v));
  }
  __syncthreads();
  const int wid = tid >> 5, lane = tid & 31;
  const int o = blockIdx.x * 8 + wid;          // grid.x = 128 -> o in [0,1024)
  const float* wr = Wt + (size_t)o * CTC;
  float acc = 0.f;
#pragma unroll
  for (int itr = 0; itr < 4; ++itr) {
    int k = itr * 128 + lane * 4;
    float4 wv = *(const float4*)(wr + k);
    acc += wv.x * st[k] + wv.y * st[k + 1] + wv.z * st[k + 2] + wv.w * st[k + 3];
  }
#pragma unroll
  for (int off = 16; off; off >>= 1) acc += __shfl_xor_sync(0xffffffffu, acc, off);
  if (lane == 0) g_film[b * 1024 + o] = acc + bt[o];
}

// ---------------- kernel 2: LayerNorm + FiLM + seq mask ---------------------
__global__ void __launch_bounds__(128) ln_film_kernel(
    const float* __restrict__ x, const float* __restrict__ gamma,
    const float* __restrict__ seq_mask) {
  const int row = blockIdx.x;          // b*N+i
  const int b = row >> 10;
  const int tid = threadIdx.x;         // 128, 4 elems each
  const float* xr = x + (size_t)row * CD;
  float4 xv = *(const float4*)(xr + tid * 4);
  float s = xv.x + xv.y + xv.z + xv.w;
  float sq = xv.x * xv.x + xv.y * xv.y + xv.z * xv.z + xv.w * xv.w;
#pragma unroll
  for (int off = 16; off; off >>= 1) {
    s  += __shfl_xor_sync(0xffffffffu, s, off);
    sq += __shfl_xor_sync(0xffffffffu, sq, off);
  }
  __shared__ float rs[4], rq[4];
  const int w = tid >> 5;
  if ((tid & 31) == 0) { rs[w] = s; rq[w] = sq; }
  __syncthreads();
  s = rs[0] + rs[1] + rs[2] + rs[3];
  sq = rq[0] + rq[1] + rq[2] + rq[3];
  const float mu = s * (1.f / 512.f);
  const float var = sq * (1.f / 512.f) - mu * mu;
  const float rstd = rsqrtf(var + 1e-5f);
  float4 g = *(const float4*)(gamma + tid * 4);
  const float* fl = g_film + b * 1024;
  float4 sc = *(const float4*)(fl + tid * 4);
  float4 sh = *(const float4*)(fl + 512 + tid * 4);
  const float msk = seq_mask[row];
  float4 o;
  o.x = (((xv.x - mu) * rstd) * g.x * (sc.x + 1.f) + sh.x) * msk;
  o.y = (((xv.y - mu) * rstd) * g.y * (sc.y + 1.f) + sh.y) * msk;
  o.z = (((xv.z - mu) * rstd) * g.z * (sc.z + 1.f) + sh.z) * msk;
  o.w = (((xv.w - mu) * rstd) * g.w * (sc.w + 1.f) + sh.w) * msk;
  *(float4*)(g_xn + (size_t)row * CD + tid * 4) = o;
}

// ---------------- generic fp32 GEMM: C[m,n] = sum_k A[m,k]*W[n,k] -----------
// 128x128 tile, BK=16, 256 threads, 8x8 microtile.
// mode 0: -> g_q (*0.125, [B,H,N,DH]); mode 1: -> g_k/g_v; mode 2: -> out*mask
__global__ void __launch_bounds__(256) gemm_kernel(
    const float* __restrict__ A, const float* __restrict__ W,
    float* __restrict__ Cout, const float* __restrict__ seq_mask, int mode) {
  __shared__ float As[16][132];
  __shared__ float Bs[16][132];
  const int tid = threadIdx.x;
  const int mBase = blockIdx.y << 7;
  const int nBase = blockIdx.x << 7;
  const int ty = tid >> 4, tx = tid & 15;
  const int K = 512;
  float acc[8][8];
#pragma unroll
  for (int r = 0; r < 8; ++r)
#pragma unroll
    for (int c = 0; c < 8; ++c) acc[r][c] = 0.f;

  for (int kb = 0; kb < K; kb += 16) {
#pragma unroll
    for (int itl = 0; itl < 2; ++itl) {
      int f = tid + (itl << 8);
      int row = f >> 2;
      int kq = (f & 3) << 2;
      float4 av = *(const float4*)(A + (size_t)(mBase + row) * K + kb + kq);
      As[kq + 0][row] = av.x; As[kq + 1][row] = av.y;
      As[kq + 2][row] = av.z; As[kq + 3][row] = av.w;
      float4 bv = *(const float4*)(W + (size_t)(nBase + row) * K + kb + kq);
      Bs[kq + 0][row] = bv.x; Bs[kq + 1][row] = bv.y;
      Bs[kq + 2][row] = bv.z; Bs[kq + 3][row] = bv.w;
    }
    __syncthreads();
#pragma unroll
    for (int kk = 0; kk < 16; ++kk) {
      float4 a0 = *(const float4*)(&As[kk][ty * 8]);
      float4 a1 = *(const float4*)(&As[kk][ty * 8 + 4]);
      float4 b0 = *(const float4*)(&Bs[kk][tx * 8]);
      float4 b1 = *(const float4*)(&Bs[kk][tx * 8 + 4]);
      float av[8] = {a0.x, a0.y, a0.z, a0.w, a1.x, a1.y, a1.z, a1.w};
      float bv[8] = {b0.x, b0.y, b0.z, b0.w, b1.x, b1.y, b1.z, b1.w};
#pragma unroll
      for (int r = 0; r < 8; ++r)
#pragma unroll
        for (int c = 0; c < 8; ++c) acc[r][c] += av[r] * bv[c];
    }
    __syncthreads();
  }

#pragma unroll
  for (int r = 0; r < 8; ++r) {
    const int m = mBase + ty * 8 + r;
    const int b = m >> 10, i = m & 1023;
    if (mode == 2) {
      const float msk = seq_mask[m];
      float* dst = Cout + (size_t)m * 512 + nBase + tx * 8;
      float4 o0 = make_float4(acc[r][0] * msk, acc[r][1] * msk,
                              acc[r][2] * msk, acc[r][3] * msk);
      float4 o1 = make_float4(acc[r][4] * msk, acc[r][5] * msk,
                              acc[r][6] * msk, acc[r][7] * msk);
      *(float4*)dst = o0;
      *(float4*)(dst + 4) = o1;
    } else if (mode == 0) {
      const int n0 = nBase + tx * 8;
      const int h = n0 >> 6, d = n0 & 63;
      float* dst = g_q + (((size_t)(b * 8 + h)) * 1024 + i) * 64 + d;
      float4 o0 = make_float4(acc[r][0] * 0.125f, acc[r][1] * 0.125f,
                              acc[r][2] * 0.125f, acc[r][3] * 0.125f);
      float4 o1 = make_float4(acc[r][4] * 0.125f, acc[r][5] * 0.125f,
                              acc[r][6] * 0.125f, acc[r][7] * 0.125f);
      *(float4*)dst = o0;
      *(float4*)(dst + 4) = o1;
    } else {
      const int n0 = nBase + tx * 8;
      float* base = (n0 < 512) ? g_k : g_v;
      const int n2 = n0 & 511;
      const int h = n2 >> 6, d = n2 & 63;
      float* dst = base + (((size_t)(b * 8 + h)) * 1024 + i) * 64 + d;
      float4 o0 = make_float4(acc[r][0], acc[r][1], acc[r][2], acc[r][3]);
      float4 o1 = make_float4(acc[r][4], acc[r][5], acc[r][6], acc[r][7]);
      *(float4*)dst = o0;
      *(float4*)(dst + 4) = o1;
    }
  }
}

// ---------------- kernel 5: bias projection (+ bb + mask fold) --------------
// g_bias[b,h,i,j] = sum_a ab[b,a,i,j]*Wb[h,a] + bb[h] - (1-mi*mj)*1e6
__global__ void __launch_bounds__(256) bias_kernel(
    const float* __restrict__ ab, const float* __restrict__ Wb,
    const float* __restrict__ bb, const float* __restrict__ seq_mask) {
  __shared__ float sWb[128];
  __shared__ float sbb[8];
  const int i = blockIdx.x;
  const int b = blockIdx.y;
  const int tid = threadIdx.x;
  if (tid < 128) sWb[tid] = Wb[tid];
  if (tid < 8) sbb[tid] = bb[tid];
  __syncthreads();
  const int j0 = tid << 2;
  float acc[8][4];
#pragma unroll
  for (int h = 0; h < 8; ++h) {
    float v = sbb[h];
    acc[h][0] = v; acc[h][1] = v; acc[h][2] = v; acc[h][3] = v;
  }
  const float* abp = ab + ((size_t)b * 16 * 1024 + i) * 1024 + j0;
#pragma unroll 4
  for (int a = 0; a < 16; ++a) {
    float4 v = *(const float4*)(abp + (size_t)a * 1024 * 1024);
#pragma unroll
    for (int h = 0; h < 8; ++h) {
      float w = sWb[h * 16 + a];
      acc[h][0] += w * v.x; acc[h][1] += w * v.y;
      acc[h][2] += w * v.z; acc[h][3] += w * v.w;
    }
  }
  const float mi = seq_mask[b * 1024 + i];
  float4 mj = *(const float4*)(seq_mask + b * 1024 + j0);
  const float p0 = -(1.f - mi * mj.x) * 1e6f;
  const float p1 = -(1.f - mi * mj.y) * 1e6f;
  const float p2 = -(1.f - mi * mj.z) * 1e6f;
  const float p3 = -(1.f - mi * mj.w) * 1e6f;
  float* outp = g_bias + ((size_t)(b * 8) * 1024 + i) * 1024 + j0;
#pragma unroll
  for (int h = 0; h < 8; ++h) {
    float4 o = make_float4(acc[h][0] + p0, acc[h][1] + p1,
                           acc[h][2] + p2, acc[h][3] + p3);
    *(float4*)(outp + (size_t)h * 1024 * 1024) = o;
  }
}

// ---------------- kernel 6: flash attention (fp32, bias from g_bias) --------
// grid (N/64, B*H), 128 threads. Br=Bc=64, per-thread 4 rows x 8 cols.
#define ATTN_SMEM_FLOATS (3 * 64 * 64 + 2 * 64 * 68)
__global__ void __launch_bounds__(128) attn_kernel() {
  extern __shared__ float sm[];
  float* Qs = sm;                 // [d][i]  64x64
  float* Ks = sm + 4096;          // [d][j]  64x64
  float* Vs = sm + 8192;          // [j][d]  64x64
  float* Bs = sm + 12288;         // [i][j]  64x68 (padded)
  float* Ps = sm + 12288 + 64 * 68;  // [j][i] 64x68 (padded)

  const int bh = blockIdx.y;
  const int itile = blockIdx.x;
  const int tid = threadIdx.x;
  const int tr = tid >> 3, tc = tid & 7;
  const int i0 = tr * 4;
  const int jc = tc * 8;

  const float* qg = g_q + ((size_t)bh * CN + itile * 64) * CDH;
#pragma unroll
  for (int f = tid; f < 1024; f += 128) {
    int row = f >> 4;
    int dq = (f & 15) << 2;
    float4 v = *(const float4*)(qg + row * 64 + dq);
    Qs[(dq + 0) * 64 + row] = v.x;
    Qs[(dq + 1) * 64 + row] = v.y;
    Qs[(dq + 2) * 64 + row] = v.z;
    Qs[(dq + 3) * 64 + row] = v.w;
  }

  float O[4][8];
  float mr[4], lr[4];
#pragma unroll
  for (int r = 0; r < 4; ++r) {
    mr[r] = -1e30f;
    lr[r] = 0.f;
#pragma unroll
    for (int c = 0; c < 8; ++c) O[r][c] = 0.f;
  }

  const float* kg = g_k + (size_t)bh * CN * CDH;
  const float* vg = g_v + (size_t)bh * CN * CDH;
  const float* bg = g_bias + ((size_t)bh * CN + itile * 64) * CN;

  for (int jt = 0; jt < 16; ++jt) {
    __syncthreads();   // prior iteration fully consumed K/V/B/P
    const float* kgt = kg + jt * 64 * 64;
    const float* vgt = vg + jt * 64 * 64;
#pragma unroll
    for (int f = tid; f < 1024; f += 128) {
      int row = f >> 4;
      int dq = (f & 15) << 2;
      float4 kv = *(const float4*)(kgt + row * 64 + dq);
      Ks[(dq + 0) * 64 + row] = kv.x;
      Ks[(dq + 1) * 64 + row] = kv.y;
      Ks[(dq + 2) * 64 + row] = kv.z;
      Ks[(dq + 3) * 64 + row] = kv.w;
      *(float4*)(Vs + row * 64 + dq) = *(const float4*)(vgt + row * 64 + dq);
      float4 bv = *(const float4*)(bg + (size_t)row * CN + jt * 64 + dq);
      *(float4*)(Bs + row * 68 + dq) = bv;
    }
    __syncthreads();

    float S[4][8];
#pragma unroll
    for (int r = 0; r < 4; ++r) {
      float4 b0 = *(const float4*)(Bs + (i0 + r) * 68 + jc);
      float4 b1 = *(const float4*)(Bs + (i0 + r) * 68 + jc + 4);
      S[r][0] = b0.x; S[r][1] = b0.y; S[r][2] = b0.z; S[r][3] = b0.w;
      S[r][4] = b1.x; S[r][5] = b1.y; S[r][6] = b1.z; S[r][7] = b1.w;
    }
#pragma unroll 4
    for (int kk = 0; kk < 64; ++kk) {
      float4 q4 = *(const float4*)(Qs + kk * 64 + i0);
      float4 ka = *(const float4*)(Ks + kk * 64 + jc);
      float4 kb = *(const float4*)(Ks + kk * 64 + jc + 4);
      float qa[4] = {q4.x, q4.y, q4.z, q4.w};
      float kv[8] = {ka.x, ka.y, ka.z, ka.w, kb.x, kb.y, kb.z, kb.w};
#pragma unroll
      for (int r = 0; r < 4; ++r)
#pragma unroll
        for (int c = 0; c < 8; ++c) S[r][c] += qa[r] * kv[c];
    }
    // online softmax (row groups of 8 lanes, aligned within warp)
#pragma unroll
    for (int r = 0; r < 4; ++r) {
      float rm = S[r][0];
#pragma unroll
      for (int c = 1; c < 8; ++c) rm = fmaxf(rm, S[r][c]);
      rm = fmaxf(rm, __shfl_xor_sync(0xffffffffu, rm, 1));
      rm = fmaxf(rm, __shfl_xor_sync(0xffffffffu, rm, 2));
      rm = fmaxf(rm, __shfl_xor_sync(0xffffffffu, rm, 4));
      const float mn = fmaxf(mr[r], rm);
      const float alpha = __expf(mr[r] - mn);
      mr[r] = mn;
      float rsum = 0.f;
#pragma unroll
      for (int c = 0; c < 8; ++c) {
        S[r][c] = __expf(S[r][c] - mn);
        rsum += S[r][c];
      }
      rsum += __shfl_xor_sync(0xffffffffu, rsum, 1);
      rsum += __shfl_xor_sync(0xffffffffu, rsum, 2);
      rsum += __shfl_xor_sync(0xffffffffu, rsum, 4);
      lr[r] = lr[r] * alpha + rsum;
#pragma unroll
      for (int c = 0; c < 8; ++c) O[r][c] *= alpha;
    }
    // write P transposed for PV pass
#pragma unroll
    for (int c = 0; c < 8; ++c) {
      int j = jc + c;
      *(float4*)(Ps + j * 68 + i0) =
          make_float4(S[0][c], S[1][c], S[2][c], S[3][c]);
    }
    __syncthreads();
#pragma unroll 4
    for (int jj = 0; jj < 64; ++jj) {
      float4 p4 = *(const float4*)(Ps + jj * 68 + i0);
      float4 va = *(const float4*)(Vs + jj * 64 + jc);
      float4 vb = *(const float4*)(Vs + jj * 64 + jc + 4);
      float pa[4] = {p4.x, p4.y, p4.z, p4.w};
      float vv[8] = {va.x, va.y, va.z, va.w, vb.x, vb.y, vb.z, vb.w};
#pragma unroll
      for (int r = 0; r < 4; ++r)
#pragma unroll
        for (int c = 0; c < 8; ++c) O[r][c] += pa[r] * vv[c];
    }
  }

  const int b = bh >> 3, h = bh & 7;
#pragma unroll
  for (int r = 0; r < 4; ++r) {
    const float inv = 1.f / lr[r];
    const int i = itile * 64 + i0 + r;
    float* og = g_o + ((size_t)b * CN + i) * 512 + h * 64 + jc;
    *(float4*)og = make_float4(O[r][0] * inv, O[r][1] * inv,
                               O[r][2] * inv, O[r][3] * inv);
    *(float4*)(og + 4) = make_float4(O[r][4] * inv, O[r][5] * inv,
                                     O[r][6] * inv, O[r][7] * inv);
  }
}

// ---------------- launch --------------------------------------------------
extern "C" void kernel_launch(void* const* d_in, const int* in_sizes, int n_in,
                              void* d_out, int out_size) {
  const float* x        = (const float*)d_in[0];
  const float* timep    = (const float*)d_in[1];
  const float* ab       = (const float*)d_in[2];
  const float* seq_mask = (const float*)d_in[3];
  const float* gamma    = (const float*)d_in[4];
  const float* Wt       = (const float*)d_in[5];
  const float* bt       = (const float*)d_in[6];
  const float* Wq       = (const float*)d_in[7];
  const float* Wkv      = (const float*)d_in[8];
  const float* Wo       = (const float*)d_in[9];
  const float* Wb       = (const float*)d_in[10];
  const float* bb       = (const float*)d_in[11];
  float* out = (float*)d_out;

  void* p_xn = nullptr;
  void* p_o  = nullptr;
  cudaGetSymbolAddress(&p_xn, g_xn);
  cudaGetSymbolAddress(&p_o, g_o);

  const int attn_smem = ATTN_SMEM_FLOATS * (int)sizeof(float);  // 83968 B
  cudaFuncSetAttribute(attn_kernel, cudaFuncAttributeMaxDynamicSharedMemorySize,
                       attn_smem);

  film_kernel<<<dim3(128, CB), 256>>>(timep, Wt, bt);
  ln_film_kernel<<<CB * CN, 128>>>(x, gamma, seq_mask);
  // Q = xn @ Wq^T (M=4096, N=512)
  gemm_kernel<<<dim3(4, 32), 256>>>((const float*)p_xn, Wq, nullptr, seq_mask, 0);
  // KV = x @ Wkv^T (M=4096, N=1024)  -- raw x (reference uses pre-norm ctx)
  gemm_kernel<<<dim3(8, 32), 256>>>(x, Wkv, nullptr, seq_mask, 1);
  // bias projection
  bias_kernel<<<dim3(CN, CB), 256>>>(ab, Wb, bb, seq_mask);
  // fused attention
  attn_kernel<<<dim3(CN / 64, CB * CH), 128, attn_smem>>>();
  // out = O @ Wo^T, * seq_mask
  gemm_kernel<<<dim3(4, 32), 256>>>((const float*)p_o, Wo, out, seq_mask, 2);
}

// round 4
// speedup vs baseline: 1.0920x; 1.0920x over previous
#include <cuda_runtime.h>
#include <cuda_bf16.h>
#include <mma.h>

using namespace nvcuda;
typedef __nv_bfloat16 bf16;

#define CB 4
#define CN 1024
#define CD 512
#define CH 8
#define CDH 64
#define CTC 512

// ---------------- scratch (device globals; allocations are forbidden) -------
__device__ float g_film[CB * 2 * CD];
__device__ bf16  g_xh[CB * CN * CD],  g_xl[CB * CN * CD];     // raw x hi/lo
__device__ bf16  g_xnh[CB * CN * CD], g_xnl[CB * CN * CD];    // ln+film hi/lo
__device__ bf16  g_wqh[CD * CD],      g_wql[CD * CD];
__device__ bf16  g_wkvh[2 * CD * CD], g_wkvl[2 * CD * CD];
__device__ bf16  g_woh[CD * CD],      g_wol[CD * CD];
__device__ bf16  g_qh[CB * CH * CN * CDH], g_ql[CB * CH * CN * CDH];
__device__ bf16  g_kh[CB * CH * CN * CDH], g_kl[CB * CH * CN * CDH];
__device__ bf16  g_vh[CB * CH * CN * CDH], g_vl[CB * CH * CN * CDH];
__device__ bf16  g_oh[CB * CN * CD],  g_ol[CB * CN * CD];
__device__ float g_bias[CB * CH * CN * CN];                   // 128 MB

__device__ __forceinline__ void split2(float v, bf16& h, bf16& l) {
  h = __float2bfloat16(v);
  l = __float2bfloat16(v - __bfloat162float(h));
}

// ---------------- fp32 -> hi/lo bf16 conversion -----------------------------
__global__ void __launch_bounds__(256) convert_hl(
    const float* __restrict__ src, bf16* __restrict__ hp, bf16* __restrict__ lp) {
  int i = (blockIdx.x * 256 + threadIdx.x) * 4;
  float4 v = *(const float4*)(src + i);
  bf16 h0, h1, h2, h3, l0, l1, l2, l3;
  split2(v.x, h0, l0); split2(v.y, h1, l1);
  split2(v.z, h2, l2); split2(v.w, h3, l3);
  ((__nv_bfloat162*)(hp + i))[0] = __halves2bfloat162(h0, h1);
  ((__nv_bfloat162*)(hp + i))[1] = __halves2bfloat162(h2, h3);
  ((__nv_bfloat162*)(lp + i))[0] = __halves2bfloat162(l0, l1);
  ((__nv_bfloat162*)(lp + i))[1] = __halves2bfloat162(l2, l3);
}

// ---------------- FiLM params: t = silu(time) @ Wt^T + bt -------------------
__global__ void __launch_bounds__(256) film_kernel(
    const float* __restrict__ timep, const float* __restrict__ Wt,
    const float* __restrict__ bt) {
  const int b = blockIdx.y;
  __shared__ float st[CTC];
  const int tid = threadIdx.x;
  for (int t = tid; t < CTC; t += 256) {
    float v = timep[b * CTC + t];
    st[t] = v / (1.f + __expf(-v));
  }
  __syncthreads();
  const int wid = tid >> 5, lane = tid & 31;
  const int o = blockIdx.x * 8 + wid;
  const float* wr = Wt + (size_t)o * CTC;
  float acc = 0.f;
#pragma unroll
  for (int itr = 0; itr < 4; ++itr) {
    int k = itr * 128 + lane * 4;
    float4 wv = *(const float4*)(wr + k);
    acc += wv.x * st[k] + wv.y * st[k + 1] + wv.z * st[k + 2] + wv.w * st[k + 3];
  }
#pragma unroll
  for (int off = 16; off; off >>= 1) acc += __shfl_xor_sync(0xffffffffu, acc, off);
  if (lane == 0) g_film[b * 1024 + o] = acc + bt[o];
}

// ---------------- LayerNorm + FiLM + mask -> hi/lo bf16 ---------------------
__global__ void __launch_bounds__(128) ln_film_kernel(
    const float* __restrict__ x, const float* __restrict__ gamma,
    const float* __restrict__ seq_mask) {
  const int row = blockIdx.x;
  const int b = row >> 10;
  const int tid = threadIdx.x;
  const float* xr = x + (size_t)row * CD;
  float4 xv = *(const float4*)(xr + tid * 4);
  float s = xv.x + xv.y + xv.z + xv.w;
  float sq = xv.x * xv.x + xv.y * xv.y + xv.z * xv.z + xv.w * xv.w;
#pragma unroll
  for (int off = 16; off; off >>= 1) {
    s  += __shfl_xor_sync(0xffffffffu, s, off);
    sq += __shfl_xor_sync(0xffffffffu, sq, off);
  }
  __shared__ float rs[4], rq[4];
  const int w = tid >> 5;
  if ((tid & 31) == 0) { rs[w] = s; rq[w] = sq; }
  __syncthreads();
  s = rs[0] + rs[1] + rs[2] + rs[3];
  sq = rq[0] + rq[1] + rq[2] + rq[3];
  const float mu = s * (1.f / 512.f);
  const float var = sq * (1.f / 512.f) - mu * mu;
  const float rstd = rsqrtf(var + 1e-5f);
  float4 g = *(const float4*)(gamma + tid * 4);
  const float* fl = g_film + b * 1024;
  float4 sc = *(const float4*)(fl + tid * 4);
  float4 sh = *(const float4*)(fl + 512 + tid * 4);
  const float msk = seq_mask[row];
  float4 o;
  o.x = (((xv.x - mu) * rstd) * g.x * (sc.x + 1.f) + sh.x) * msk;
  o.y = (((xv.y - mu) * rstd) * g.y * (sc.y + 1.f) + sh.y) * msk;
  o.z = (((xv.z - mu) * rstd) * g.z * (sc.z + 1.f) + sh.z) * msk;
  o.w = (((xv.w - mu) * rstd) * g.w * (sc.w + 1.f) + sh.w) * msk;
  const int idx = row * CD + tid * 4;
  bf16 h0, h1, h2, h3, l0, l1, l2, l3;
  split2(o.x, h0, l0); split2(o.y, h1, l1);
  split2(o.z, h2, l2); split2(o.w, h3, l3);
  ((__nv_bfloat162*)(g_xnh + idx))[0] = __halves2bfloat162(h0, h1);
  ((__nv_bfloat162*)(g_xnh + idx))[1] = __halves2bfloat162(h2, h3);
  ((__nv_bfloat162*)(g_xnl + idx))[0] = __halves2bfloat162(l0, l1);
  ((__nv_bfloat162*)(g_xnl + idx))[1] = __halves2bfloat162(l2, l3);
}

// ---------------- tensor-core GEMM: C[m,n] = sum_k A[m,k]*W[n,k] ------------
// bf16 hi/lo split, 3 MMAs per tile pair. Block 128x128, 8 warps (2M x 4N),
// warp tile 64x32. K staged 32 at a time.
#define GLD 40
#define GEMM_SMEM 73728
__global__ void __launch_bounds__(256) mma_gemm(
    const bf16* __restrict__ Ah, const bf16* __restrict__ Al,
    const bf16* __restrict__ Bh, const bf16* __restrict__ Bl,
    float* __restrict__ Cout, const float* __restrict__ seq_mask, int mode) {
  extern __shared__ char smraw[];
  bf16* sAh = (bf16*)smraw;            // [128][GLD]
  bf16* sAl = sAh + 128 * GLD;
  bf16* sBh = sAl + 128 * GLD;
  bf16* sBl = sBh + 128 * GLD;
  float* sEp = (float*)smraw;          // epilogue reuse: 8 warps x [64][36]

  const int tid = threadIdx.x;
  const int wid = tid >> 5, lane = tid & 31;
  const int wM = wid >> 2, wN = wid & 3;       // 2 x 4 warp grid
  const int mBase = blockIdx.y << 7;
  const int nBase = blockIdx.x << 7;

  wmma::fragment<wmma::accumulator, 16, 16, 16, float> acc[4][2];
#pragma unroll
  for (int mf = 0; mf < 4; ++mf)
#pragma unroll
    for (int nf = 0; nf < 2; ++nf) wmma::fill_fragment(acc[mf][nf], 0.f);

  for (int kb = 0; kb < 512; kb += 32) {
#pragma unroll
    for (int it = 0; it < 2; ++it) {
      int e = tid + it * 256;                  // 512 uint4 per array
      int row = e >> 2;
      int c8 = (e & 3) << 3;
      size_t go = (size_t)(mBase + row) * 512 + kb + c8;
      *(uint4*)(sAh + row * GLD + c8) = *(const uint4*)(Ah + go);
      *(uint4*)(sAl + row * GLD + c8) = *(const uint4*)(Al + go);
      size_t gob = (size_t)(nBase + row) * 512 + kb + c8;
      *(uint4*)(sBh + row * GLD + c8) = *(const uint4*)(Bh + gob);
      *(uint4*)(sBl + row * GLD + c8) = *(const uint4*)(Bl + gob);
    }
    __syncthreads();
#pragma unroll
    for (int ks = 0; ks < 32; ks += 16) {
#pragma unroll
      for (int nf = 0; nf < 2; ++nf) {
        wmma::fragment<wmma::matrix_b, 16, 16, 16, bf16, wmma::col_major> bh, bl;
        const bf16* bp = sBh + (wN * 32 + nf * 16) * GLD + ks;
        wmma::load_matrix_sync(bh, bp, GLD);
        wmma::load_matrix_sync(bl, sBl + (wN * 32 + nf * 16) * GLD + ks, GLD);
#pragma unroll
        for (int mf = 0; mf < 4; ++mf) {
          wmma::fragment<wmma::matrix_a, 16, 16, 16, bf16, wmma::row_major> ah, al;
          wmma::load_matrix_sync(ah, sAh + (wM * 64 + mf * 16) * GLD + ks, GLD);
          wmma::load_matrix_sync(al, sAl + (wM * 64 + mf * 16) * GLD + ks, GLD);
          wmma::mma_sync(acc[mf][nf], ah, bh, acc[mf][nf]);
          wmma::mma_sync(acc[mf][nf], ah, bl, acc[mf][nf]);
          wmma::mma_sync(acc[mf][nf], al, bh, acc[mf][nf]);
        }
      }
    }
    __syncthreads();
  }

  // epilogue: stage warp tile to smem, then scatter
  float* sW = sEp + wid * 64 * 36;
#pragma unroll
  for (int mf = 0; mf < 4; ++mf)
#pragma unroll
    for (int nf = 0; nf < 2; ++nf)
      wmma::store_matrix_sync(sW + mf * 16 * 36 + nf * 16, acc[mf][nf], 36,
                              wmma::mem_row_major);
  __syncwarp();
#pragma unroll 4
  for (int it = 0; it < 64; ++it) {
    int r = it, c = lane;
    float v = sW[r * 36 + c];
    int m = mBase + wM * 64 + r;
    int n = nBase + wN * 32 + c;
    int b = m >> 10, i = m & 1023;
    if (mode == 2) {
      Cout[(size_t)m * 512 + n] = v * seq_mask[m];
    } else if (mode == 0) {
      v *= 0.125f;
      int h = n >> 6, d = n & 63;
      size_t idx = (((size_t)(b * 8 + h)) * 1024 + i) * 64 + d;
      bf16 hh, ll; split2(v, hh, ll);
      g_qh[idx] = hh; g_ql[idx] = ll;
    } else {
      int n2 = n & 511;
      int h = n2 >> 6, d = n2 & 63;
      size_t idx = (((size_t)(b * 8 + h)) * 1024 + i) * 64 + d;
      bf16 hh, ll; split2(v, hh, ll);
      if (n < 512) { g_kh[idx] = hh; g_kl[idx] = ll; }
      else         { g_vh[idx] = hh; g_vl[idx] = ll; }
    }
  }
}

// ---------------- bias projection (+ bb + mask fold) ------------------------
__global__ void __launch_bounds__(256) bias_kernel(
    const float* __restrict__ ab, const float* __restrict__ Wb,
    const float* __restrict__ bb, const float* __restrict__ seq_mask) {
  __shared__ float sWb[128];
  __shared__ float sbb[8];
  const int i = blockIdx.x;
  const int b = blockIdx.y;
  const int tid = threadIdx.x;
  if (tid < 128) sWb[tid] = Wb[tid];
  if (tid < 8) sbb[tid] = bb[tid];
  __syncthreads();
  const int j0 = tid << 2;
  float acc[8][4];
#pragma unroll
  for (int h = 0; h < 8; ++h) {
    float v = sbb[h];
    acc[h][0] = v; acc[h][1] = v; acc[h][2] = v; acc[h][3] = v;
  }
  const float* abp = ab + ((size_t)b * 16 * 1024 + i) * 1024 + j0;
#pragma unroll 4
  for (int a = 0; a < 16; ++a) {
    float4 v = *(const float4*)(abp + (size_t)a * 1024 * 1024);
#pragma unroll
    for (int h = 0; h < 8; ++h) {
      float w = sWb[h * 16 + a];
      acc[h][0] += w * v.x; acc[h][1] += w * v.y;
      acc[h][2] += w * v.z; acc[h][3] += w * v.w;
    }
  }
  const float mi = seq_mask[b * 1024 + i];
  float4 mj = *(const float4*)(seq_mask + b * 1024 + j0);
  const float p0 = -(1.f - mi * mj.x) * 1e6f;
  const float p1 = -(1.f - mi * mj.y) * 1e6f;
  const float p2 = -(1.f - mi * mj.z) * 1e6f;
  const float p3 = -(1.f - mi * mj.w) * 1e6f;
  float* outp = g_bias + ((size_t)(b * 8) * 1024 + i) * 1024 + j0;
#pragma unroll
  for (int h = 0; h < 8; ++h) {
    float4 o = make_float4(acc[h][0] + p0, acc[h][1] + p1,
                           acc[h][2] + p2, acc[h][3] + p3);
    *(float4*)(outp + (size_t)h * 1024 * 1024) = o;
  }
}

// ---------------- tensor-core flash attention -------------------------------
// grid (16, 32), 128 threads (4 warps). 64x64 tiles. Bias tile is staged into
// Ss and used as the initial QK^T accumulator. O lives in smem, reloaded as
// the PV accumulator fragment.
#define ATTN_SMEM (8 * 4096 * 2 + 2 * 64 * 68 * 4)  // 100352 B
__global__ void __launch_bounds__(128) attn_mma() {
  extern __shared__ char smraw[];
  bf16* Qh = (bf16*)smraw;
  bf16* Ql = Qh + 4096;
  bf16* Kh = Ql + 4096;
  bf16* Kl = Kh + 4096;
  bf16* Vh = Kl + 4096;
  bf16* Vl = Vh + 4096;
  bf16* Ph = Vl + 4096;
  bf16* Pl = Ph + 4096;
  float* Ss = (float*)(Pl + 4096);   // [64][68]
  float* Os = Ss + 64 * 68;          // [64][68]

  const int bh = blockIdx.y;
  const int itile = blockIdx.x;
  const int tid = threadIdx.x;
  const int wid = tid >> 5;

  // load Q tile (hi/lo)
  {
    const bf16* qh = g_qh + (size_t)bh * 65536 + itile * 4096;
    const bf16* ql = g_ql + (size_t)bh * 65536 + itile * 4096;
#pragma unroll
    for (int it = 0; it < 4; ++it) {
      int e = tid + it * 128;        // 512 uint4
      *(uint4*)(Qh + e * 8) = *(const uint4*)(qh + e * 8);
      *(uint4*)(Ql + e * 8) = *(const uint4*)(ql + e * 8);
    }
  }
  // zero O
  for (int e = tid; e < 64 * 68; e += 128) Os[e] = 0.f;

  const int r = tid >> 1;            // softmax row
  const int half = tid & 1;
  const int c0 = half * 32;
  float mr = -1e30f, lr = 0.f;

  const bf16* kh = g_kh + (size_t)bh * 65536;
  const bf16* kl = g_kl + (size_t)bh * 65536;
  const bf16* vh = g_vh + (size_t)bh * 65536;
  const bf16* vl = g_vl + (size_t)bh * 65536;
  const float* bg = g_bias + ((size_t)bh * 1024 + itile * 64) * 1024;

  for (int jt = 0; jt < 16; ++jt) {
    __syncthreads();
    // stage K/V hi/lo + bias tile
#pragma unroll
    for (int it = 0; it < 4; ++it) {
      int e = tid + it * 128;
      *(uint4*)(Kh + e * 8) = *(const uint4*)(kh + jt * 4096 + e * 8);
      *(uint4*)(Kl + e * 8) = *(const uint4*)(kl + jt * 4096 + e * 8);
      *(uint4*)(Vh + e * 8) = *(const uint4*)(vh + jt * 4096 + e * 8);
      *(uint4*)(Vl + e * 8) = *(const uint4*)(vl + jt * 4096 + e * 8);
    }
#pragma unroll
    for (int it = 0; it < 8; ++it) {
      int e = tid + it * 128;        // 1024 float4
      int row = e >> 4, cc = (e & 15) << 2;
      *(float4*)(Ss + row * 68 + cc) =
          *(const float4*)(bg + (size_t)row * 1024 + jt * 64 + cc);
    }
    __syncthreads();

    // S = bias + Q K^T  (each warp: rows wid*16..+16)
    {
      wmma::fragment<wmma::accumulator, 16, 16, 16, float> sacc[4];
#pragma unroll
      for (int nf = 0; nf < 4; ++nf)
        wmma::load_matrix_sync(sacc[nf], Ss + (wid * 16) * 68 + nf * 16, 68,
                               wmma::mem_row_major);
#pragma unroll
      for (int ks = 0; ks < 4; ++ks) {
        wmma::fragment<wmma::matrix_a, 16, 16, 16, bf16, wmma::row_major> ah, al;
        wmma::load_matrix_sync(ah, Qh + (wid * 16) * 64 + ks * 16, 64);
        wmma::load_matrix_sync(al, Ql + (wid * 16) * 64 + ks * 16, 64);
#pragma unroll
        for (int nf = 0; nf < 4; ++nf) {
          wmma::fragment<wmma::matrix_b, 16, 16, 16, bf16, wmma::col_major> bh2, bl2;
          wmma::load_matrix_sync(bh2, Kh + (nf * 16) * 64 + ks * 16, 64);
          wmma::load_matrix_sync(bl2, Kl + (nf * 16) * 64 + ks * 16, 64);
          wmma::mma_sync(sacc[nf], ah, bh2, sacc[nf]);
          wmma::mma_sync(sacc[nf], ah, bl2, sacc[nf]);
          wmma::mma_sync(sacc[nf], al, bh2, sacc[nf]);
        }
      }
#pragma unroll
      for (int nf = 0; nf < 4; ++nf)
        wmma::store_matrix_sync(Ss + (wid * 16) * 68 + nf * 16, sacc[nf], 68,
                                wmma::mem_row_major);
    }
    __syncthreads();

    // online softmax: 2 threads per row, 32 cols each
    {
      float rowm = -1e30f;
#pragma unroll
      for (int c = 0; c < 32; c += 4) {
        float4 v = *(const float4*)(Ss + r * 68 + c0 + c);
        rowm = fmaxf(rowm, fmaxf(fmaxf(v.x, v.y), fmaxf(v.z, v.w)));
      }
      rowm = fmaxf(rowm, __shfl_xor_sync(0xffffffffu, rowm, 1));
      const float newm = fmaxf(mr, rowm);
      const float alpha = __expf(mr - newm);
      mr = newm;
      float sum = 0.f;
#pragma unroll
      for (int c = 0; c < 32; c += 4) {
        float4 v = *(const float4*)(Ss + r * 68 + c0 + c);
        float e0 = __expf(v.x - mr), e1 = __expf(v.y - mr);
        float e2 = __expf(v.z - mr), e3 = __expf(v.w - mr);
        sum += (e0 + e1) + (e2 + e3);
        bf16 h0, h1, h2, h3, l0, l1, l2, l3;
        split2(e0, h0, l0); split2(e1, h1, l1);
        split2(e2, h2, l2); split2(e3, h3, l3);
        int po = r * 64 + c0 + c;
        ((__nv_bfloat162*)(Ph + po))[0] = __halves2bfloat162(h0, h1);
        ((__nv_bfloat162*)(Ph + po))[1] = __halves2bfloat162(h2, h3);
        ((__nv_bfloat162*)(Pl + po))[0] = __halves2bfloat162(l0, l1);
        ((__nv_bfloat162*)(Pl + po))[1] = __halves2bfloat162(l2, l3);
      }
      sum += __shfl_xor_sync(0xffffffffu, sum, 1);
      lr = lr * alpha + sum;
      // rescale O rows
#pragma unroll
      for (int c = 0; c < 32; c += 4) {
        float4 o = *(float4*)(Os + r * 68 + c0 + c);
        o.x *= alpha; o.y *= alpha; o.z *= alpha; o.w *= alpha;
        *(float4*)(Os + r * 68 + c0 + c) = o;
      }
    }
    __syncthreads();

    // O += P V
    {
      wmma::fragment<wmma::accumulator, 16, 16, 16, float> oacc[4];
#pragma unroll
      for (int df = 0; df < 4; ++df)
        wmma::load_matrix_sync(oacc[df], Os + (wid * 16) * 68 + df * 16, 68,
                               wmma::mem_row_major);
#pragma unroll
      for (int ks = 0; ks < 4; ++ks) {
        wmma::fragment<wmma::matrix_a, 16, 16, 16, bf16, wmma::row_major> ah, al;
        wmma::load_matrix_sync(ah, Ph + (wid * 16) * 64 + ks * 16, 64);
        wmma::load_matrix_sync(al, Pl + (wid * 16) * 64 + ks * 16, 64);
#pragma unroll
        for (int df = 0; df < 4; ++df) {
          wmma::fragment<wmma::matrix_b, 16, 16, 16, bf16, wmma::row_major> bh2, bl2;
          wmma::load_matrix_sync(bh2, Vh + (ks * 16) * 64 + df * 16, 64);
          wmma::load_matrix_sync(bl2, Vl + (ks * 16) * 64 + df * 16, 64);
          wmma::mma_sync(oacc[df], ah, bh2, oacc[df]);
          wmma::mma_sync(oacc[df], ah, bl2, oacc[df]);
          wmma::mma_sync(oacc[df], al, bh2, oacc[df]);
        }
      }
#pragma unroll
      for (int df = 0; df < 4; ++df)
        wmma::store_matrix_sync(Os + (wid * 16) * 68 + df * 16, oacc[df], 68,
                                wmma::mem_row_major);
    }
  }
  __syncthreads();

  // epilogue: O / l -> g_oh/g_ol at [b, i, h*64 + d]
  {
    const int b = bh >> 3, h = bh & 7;
    const float inv = 1.f / lr;
    const int m = b * 1024 + itile * 64 + r;
    bf16* oh = g_oh + (size_t)m * 512 + h * 64 + c0;
    bf16* ol = g_ol + (size_t)m * 512 + h * 64 + c0;
#pragma unroll
    for (int c = 0; c < 32; c += 4) {
      float4 o = *(const float4*)(Os + r * 68 + c0 + c);
      bf16 h0, h1, h2, h3, l0, l1, l2, l3;
      split2(o.x * inv, h0, l0); split2(o.y * inv, h1, l1);
      split2(o.z * inv, h2, l2); split2(o.w * inv, h3, l3);
      ((__nv_bfloat162*)(oh + c))[0] = __halves2bfloat162(h0, h1);
      ((__nv_bfloat162*)(oh + c))[1] = __halves2bfloat162(h2, h3);
      ((__nv_bfloat162*)(ol + c))[0] = __halves2bfloat162(l0, l1);
      ((__nv_bfloat162*)(ol + c))[1] = __halves2bfloat162(l2, l3);
    }
  }
}

// ---------------- launch ----------------------------------------------------
extern "C" void kernel_launch(void* const* d_in, const int* in_sizes, int n_in,
                              void* d_out, int out_size) {
  const float* x        = (const float*)d_in[0];
  const float* timep    = (const float*)d_in[1];
  const float* ab       = (const float*)d_in[2];
  const float* seq_mask = (const float*)d_in[3];
  const float* gamma    = (const float*)d_in[4];
  const float* Wt       = (const float*)d_in[5];
  const float* bt       = (const float*)d_in[6];
  const float* Wq       = (const float*)d_in[7];
  const float* Wkv      = (const float*)d_in[8];
  const float* Wo       = (const float*)d_in[9];
  const float* Wb       = (const float*)d_in[10];
  const float* bb       = (const float*)d_in[11];
  float* out = (float*)d_out;

  void *p_xh, *p_xl, *p_xnh, *p_xnl, *p_wqh, *p_wql, *p_wkvh, *p_wkvl,
       *p_woh, *p_wol, *p_oh, *p_ol;
  cudaGetSymbolAddress(&p_xh, g_xh);   cudaGetSymbolAddress(&p_xl, g_xl);
  cudaGetSymbolAddress(&p_xnh, g_xnh); cudaGetSymbolAddress(&p_xnl, g_xnl);
  cudaGetSymbolAddress(&p_wqh, g_wqh); cudaGetSymbolAddress(&p_wql, g_wql);
  cudaGetSymbolAddress(&p_wkvh, g_wkvh); cudaGetSymbolAddress(&p_wkvl, g_wkvl);
  cudaGetSymbolAddress(&p_woh, g_woh); cudaGetSymbolAddress(&p_wol, g_wol);
  cudaGetSymbolAddress(&p_oh, g_oh);   cudaGetSymbolAddress(&p_ol, g_ol);

  cudaFuncSetAttribute(mma_gemm, cudaFuncAttributeMaxDynamicSharedMemorySize,
                       GEMM_SMEM);
  cudaFuncSetAttribute(attn_mma, cudaFuncAttributeMaxDynamicSharedMemorySize,
                       ATTN_SMEM);

  // conversions
  convert_hl<<<2048, 256>>>(x,   (bf16*)p_xh,  (bf16*)p_xl);
  convert_hl<<<256,  256>>>(Wq,  (bf16*)p_wqh, (bf16*)p_wql);
  convert_hl<<<512,  256>>>(Wkv, (bf16*)p_wkvh, (bf16*)p_wkvl);
  convert_hl<<<256,  256>>>(Wo,  (bf16*)p_woh, (bf16*)p_wol);

  film_kernel<<<dim3(128, CB), 256>>>(timep, Wt, bt);
  ln_film_kernel<<<CB * CN, 128>>>(x, gamma, seq_mask);

  // Q = xn @ Wq^T  (-> g_qh/g_ql, pre-scaled by 1/8)
  mma_gemm<<<dim3(4, 32), 256, GEMM_SMEM>>>(
      (const bf16*)p_xnh, (const bf16*)p_xnl,
      (const bf16*)p_wqh, (const bf16*)p_wql, nullptr, seq_mask, 0);
  // KV = x @ Wkv^T (-> g_k*/g_v*)
  mma_gemm<<<dim3(8, 32), 256, GEMM_SMEM>>>(
      (const bf16*)p_xh, (const bf16*)p_xl,
      (const bf16*)p_wkvh, (const bf16*)p_wkvl, nullptr, seq_mask, 1);

  bias_kernel<<<dim3(CN, CB), 256>>>(ab, Wb, bb, seq_mask);

  attn_mma<<<dim3(16, 32), 128, ATTN_SMEM>>>();

  // out = O @ Wo^T, * mask
  mma_gemm<<<dim3(4, 32), 256, GEMM_SMEM>>>(
      (const bf16*)p_oh, (const bf16*)p_ol,
      (const bf16*)p_woh, (const bf16*)p_wol, out, seq_mask, 2);
}

// round 7
// speedup vs baseline: 2.5518x; 2.3369x over previous
#include <cuda_runtime.h>
#include <cuda_bf16.h>
#include <cstdint>
#include <mma.h>

using namespace nvcuda;
typedef __nv_bfloat16 bf16;
typedef unsigned int u32;

#define CB 4
#define CN 1024
#define CD 512
#define CH 8
#define CDH 64
#define CTC 512

// ---------------- scratch (device globals; allocations forbidden) -----------
__device__ float g_film[CB * 2 * CD];
__device__ bf16  g_xh[CB * CN * CD],  g_xl[CB * CN * CD];
__device__ bf16  g_xnh[CB * CN * CD], g_xnl[CB * CN * CD];
__device__ bf16  g_wqh[CD * CD],      g_wql[CD * CD];
__device__ bf16  g_wkvh[2 * CD * CD], g_wkvl[2 * CD * CD];
__device__ bf16  g_woh[CD * CD],      g_wol[CD * CD];
__device__ bf16  g_qh[CB * CH * CN * CDH], g_ql[CB * CH * CN * CDH];
__device__ bf16  g_kh[CB * CH * CN * CDH], g_kl[CB * CH * CN * CDH];
__device__ bf16  g_vh[CB * CH * CN * CDH], g_vl[CB * CH * CN * CDH];
__device__ bf16  g_oh[CB * CN * CD],  g_ol[CB * CN * CD];
__device__ bf16  g_biasb[CB * CH * CN * CN];            // 64 MB bf16

__device__ __forceinline__ void split2(float v, bf16& h, bf16& l) {
  h = __float2bfloat16(v);
  l = __float2bfloat16(v - __bfloat162float(h));
}
__device__ __forceinline__ u32 pack2(bf16 a, bf16 b) {
  __nv_bfloat162 t = __halves2bfloat162(a, b);
  return *(u32*)&t;
}
__device__ __forceinline__ void pack_hl2(float x, float y, u32& h, u32& l) {
  bf16 hx, lx, hy, ly;
  split2(x, hx, lx);
  split2(y, hy, ly);
  h = pack2(hx, hy);
  l = pack2(lx, ly);
}

// ---------------- PTX helpers -----------------------------------------------
__device__ __forceinline__ void cp16(u32 dst, const void* src) {
  asm volatile("cp.async.cg.shared.global [%0], [%1], 16;" :: "r"(dst), "l"(src));
}
__device__ __forceinline__ void cp_commit() {
  asm volatile("cp.async.commit_group;");
}
__device__ __forceinline__ void cp_wait0() {
  asm volatile("cp.async.wait_group 0;");
}
__device__ __forceinline__ void cp_wait1() {
  asm volatile("cp.async.wait_group 1;");
}
__device__ __forceinline__ void ldm_x4(u32& r0, u32& r1, u32& r2, u32& r3, u32 a) {
  asm volatile("ldmatrix.sync.aligned.m8n8.x4.shared.b16 {%0,%1,%2,%3}, [%4];"
               : "=r"(r0), "=r"(r1), "=r"(r2), "=r"(r3) : "r"(a));
}
__device__ __forceinline__ void ldm_x2(u32& r0, u32& r1, u32 a) {
  asm volatile("ldmatrix.sync.aligned.m8n8.x2.shared.b16 {%0,%1}, [%2];"
               : "=r"(r0), "=r"(r1) : "r"(a));
}
__device__ __forceinline__ void ldm_x2t(u32& r0, u32& r1, u32 a) {
  asm volatile("ldmatrix.sync.aligned.m8n8.x2.trans.shared.b16 {%0,%1}, [%2];"
               : "=r"(r0), "=r"(r1) : "r"(a));
}
__device__ __forceinline__ void mma_bf(float* d, const u32* a, u32 b0, u32 b1) {
  asm volatile(
      "mma.sync.aligned.m16n8k16.row.col.f32.bf16.bf16.f32 "
      "{%0,%1,%2,%3}, {%4,%5,%6,%7}, {%8,%9}, {%0,%1,%2,%3};"
      : "+f"(d[0]), "+f"(d[1]), "+f"(d[2]), "+f"(d[3])
      : "r"(a[0]), "r"(a[1]), "r"(a[2]), "r"(a[3]), "r"(b0), "r"(b1));
}

// ---------------- fp32 -> hi/lo bf16 ----------------------------------------
__global__ void __launch_bounds__(256) convert_hl(
    const float* __restrict__ src, bf16* __restrict__ hp, bf16* __restrict__ lp) {
  int i = (blockIdx.x * 256 + threadIdx.x) * 4;
  float4 v = *(const float4*)(src + i);
  bf16 h0, h1, h2, h3, l0, l1, l2, l3;
  split2(v.x, h0, l0);
  split2(v.y, h1, l1);
  split2(v.z, h2, l2);
  split2(v.w, h3, l3);
  ((__nv_bfloat162*)(hp + i))[0] = __halves2bfloat162(h0, h1);
  ((__nv_bfloat162*)(hp + i))[1] = __halves2bfloat162(h2, h3);
  ((__nv_bfloat162*)(lp + i))[0] = __halves2bfloat162(l0, l1);
  ((__nv_bfloat162*)(lp + i))[1] = __halves2bfloat162(l2, l3);
}

// ---------------- FiLM params -----------------------------------------------
__global__ void __launch_bounds__(256) film_kernel(
    const float* __restrict__ timep, const float* __restrict__ Wt,
    const float* __restrict__ bt) {
  const int b = blockIdx.y;
  __shared__ float st[CTC];
  const int tid = threadIdx.x;
  for (int t = tid; t < CTC; t += 256) {
    float v = timep[b * CTC + t];
    st[t] = v / (1.f + __expf(-v));
  }
  __syncthreads();
  const int wid = tid >> 5;
  const int lane = tid & 31;
  const int o = blockIdx.x * 8 + wid;
  const float* wr = Wt + (size_t)o * CTC;
  float acc = 0.f;
#pragma unroll
  for (int itr = 0; itr < 4; ++itr) {
    int k = itr * 128 + lane * 4;
    float4 wv = *(const float4*)(wr + k);
    acc += wv.x * st[k] + wv.y * st[k + 1] + wv.z * st[k + 2] + wv.w * st[k + 3];
  }
#pragma unroll
  for (int off = 16; off; off >>= 1) acc += __shfl_xor_sync(0xffffffffu, acc, off);
  if (lane == 0) g_film[b * 1024 + o] = acc + bt[o];
}

// ---------------- LayerNorm + FiLM + mask -> hi/lo bf16 ---------------------
__global__ void __launch_bounds__(128) ln_film_kernel(
    const float* __restrict__ x, const float* __restrict__ gamma,
    const float* __restrict__ seq_mask) {
  const int row = blockIdx.x;
  const int b = row >> 10;
  const int tid = threadIdx.x;
  const float* xr = x + (size_t)row * CD;
  float4 xv = *(const float4*)(xr + tid * 4);
  float s = xv.x + xv.y + xv.z + xv.w;
  float sq = xv.x * xv.x + xv.y * xv.y + xv.z * xv.z + xv.w * xv.w;
#pragma unroll
  for (int off = 16; off; off >>= 1) {
    s += __shfl_xor_sync(0xffffffffu, s, off);
    sq += __shfl_xor_sync(0xffffffffu, sq, off);
  }
  __shared__ float rs[4], rq[4];
  const int w = tid >> 5;
  if ((tid & 31) == 0) { rs[w] = s; rq[w] = sq; }
  __syncthreads();
  s = rs[0] + rs[1] + rs[2] + rs[3];
  sq = rq[0] + rq[1] + rq[2] + rq[3];
  const float mu = s * (1.f / 512.f);
  const float var = sq * (1.f / 512.f) - mu * mu;
  const float rstd = rsqrtf(var + 1e-5f);
  float4 g = *(const float4*)(gamma + tid * 4);
  const float* fl = g_film + b * 1024;
  float4 sc = *(const float4*)(fl + tid * 4);
  float4 sh = *(const float4*)(fl + 512 + tid * 4);
  const float msk = seq_mask[row];
  float4 o;
  o.x = (((xv.x - mu) * rstd) * g.x * (sc.x + 1.f) + sh.x) * msk;
  o.y = (((xv.y - mu) * rstd) * g.y * (sc.y + 1.f) + sh.y) * msk;
  o.z = (((xv.z - mu) * rstd) * g.z * (sc.z + 1.f) + sh.z) * msk;
  o.w = (((xv.w - mu) * rstd) * g.w * (sc.w + 1.f) + sh.w) * msk;
  const int idx = row * CD + tid * 4;
  bf16 h0, h1, h2, h3, l0, l1, l2, l3;
  split2(o.x, h0, l0);
  split2(o.y, h1, l1);
  split2(o.z, h2, l2);
  split2(o.w, h3, l3);
  ((__nv_bfloat162*)(g_xnh + idx))[0] = __halves2bfloat162(h0, h1);
  ((__nv_bfloat162*)(g_xnh + idx))[1] = __halves2bfloat162(h2, h3);
  ((__nv_bfloat162*)(g_xnl + idx))[0] = __halves2bfloat162(l0, l1);
  ((__nv_bfloat162*)(g_xnl + idx))[1] = __halves2bfloat162(l2, l3);
}

// ---------------- tensor-core GEMM (wmma, hi/lo split) ----------------------
#define GLD 40
#define GEMM_SMEM 73728
__global__ void __launch_bounds__(256) mma_gemm(
    const bf16* __restrict__ Ah, const bf16* __restrict__ Al,
    const bf16* __restrict__ Bh, const bf16* __restrict__ Bl,
    float* __restrict__ Cout, const float* __restrict__ seq_mask, int mode) {
  extern __shared__ char smem_raw[];
  bf16* sAh = (bf16*)smem_raw;
  bf16* sAl = sAh + 128 * GLD;
  bf16* sBh = sAl + 128 * GLD;
  bf16* sBl = sBh + 128 * GLD;
  float* sEp = (float*)smem_raw;

  const int tid = threadIdx.x;
  const int wid = tid >> 5;
  const int lane = tid & 31;
  const int wM = wid >> 2;
  const int wN = wid & 3;
  const int mBase = blockIdx.y << 7;
  const int nBase = blockIdx.x << 7;

  wmma::fragment<wmma::accumulator, 16, 16, 16, float> acc[4][2];
#pragma unroll
  for (int mf = 0; mf < 4; ++mf) {
#pragma unroll
    for (int nf = 0; nf < 2; ++nf) wmma::fill_fragment(acc[mf][nf], 0.f);
  }

  for (int kb = 0; kb < 512; kb += 32) {
#pragma unroll
    for (int it = 0; it < 2; ++it) {
      int e = tid + it * 256;
      int row = e >> 2;
      int c8 = (e & 3) << 3;
      size_t go = (size_t)(mBase + row) * 512 + kb + c8;
      *(uint4*)(sAh + row * GLD + c8) = *(const uint4*)(Ah + go);
      *(uint4*)(sAl + row * GLD + c8) = *(const uint4*)(Al + go);
      size_t gob = (size_t)(nBase + row) * 512 + kb + c8;
      *(uint4*)(sBh + row * GLD + c8) = *(const uint4*)(Bh + gob);
      *(uint4*)(sBl + row * GLD + c8) = *(const uint4*)(Bl + gob);
    }
    __syncthreads();
#pragma unroll
    for (int ks = 0; ks < 32; ks += 16) {
      wmma::fragment<wmma::matrix_b, 16, 16, 16, bf16, wmma::col_major> fbh[2], fbl[2];
#pragma unroll
      for (int nf = 0; nf < 2; ++nf) {
        wmma::load_matrix_sync(fbh[nf], sBh + (wN * 32 + nf * 16) * GLD + ks, GLD);
        wmma::load_matrix_sync(fbl[nf], sBl + (wN * 32 + nf * 16) * GLD + ks, GLD);
      }
#pragma unroll
      for (int mf = 0; mf < 4; ++mf) {
        wmma::fragment<wmma::matrix_a, 16, 16, 16, bf16, wmma::row_major> fah, fal;
        wmma::load_matrix_sync(fah, sAh + (wM * 64 + mf * 16) * GLD + ks, GLD);
        wmma::load_matrix_sync(fal, sAl + (wM * 64 + mf * 16) * GLD + ks, GLD);
#pragma unroll
        for (int nf = 0; nf < 2; ++nf) {
          wmma::mma_sync(acc[mf][nf], fah, fbh[nf], acc[mf][nf]);
          wmma::mma_sync(acc[mf][nf], fah, fbl[nf], acc[mf][nf]);
          wmma::mma_sync(acc[mf][nf], fal, fbh[nf], acc[mf][nf]);
        }
      }
    }
    __syncthreads();
  }

  float* sW = sEp + wid * 64 * 36;
#pragma unroll
  for (int mf = 0; mf < 4; ++mf) {
#pragma unroll
    for (int nf = 0; nf < 2; ++nf) {
      wmma::store_matrix_sync(sW + mf * 16 * 36 + nf * 16, acc[mf][nf], 36,
                              wmma::mem_row_major);
    }
  }
  __syncwarp();
  const int cp2 = (lane & 15) * 2;
  const int rsub = lane >> 4;
#pragma unroll 4
  for (int it = 0; it < 32; ++it) {
    int rr = it * 2 + rsub;
    float v0 = sW[rr * 36 + cp2];
    float v1 = sW[rr * 36 + cp2 + 1];
    int m = mBase + wM * 64 + rr;
    int n = nBase + wN * 32 + cp2;
    int b = m >> 10;
    int i = m & 1023;
    if (mode == 2) {
      float msk = seq_mask[m];
      *(float2*)(Cout + (size_t)m * 512 + n) = make_float2(v0 * msk, v1 * msk);
    } else if (mode == 0) {
      int h = n >> 6;
      int d = n & 63;
      size_t idx = (((size_t)(b * 8 + h)) * 1024 + i) * 64 + d;
      u32 ph, pl;
      pack_hl2(v0 * 0.125f, v1 * 0.125f, ph, pl);
      *(u32*)(g_qh + idx) = ph;
      *(u32*)(g_ql + idx) = pl;
    } else {
      int n2 = n & 511;
      int h = n2 >> 6;
      int d = n2 & 63;
      size_t idx = (((size_t)(b * 8 + h)) * 1024 + i) * 64 + d;
      u32 ph, pl;
      pack_hl2(v0, v1, ph, pl);
      if (n < 512) {
        *(u32*)(g_kh + idx) = ph;
        *(u32*)(g_kl + idx) = pl;
      } else {
        *(u32*)(g_vh + idx) = ph;
        *(u32*)(g_vl + idx) = pl;
      }
    }
  }
}

// ---------------- bias projection -> bf16 (+bb + mask fold) -----------------
__global__ void __launch_bounds__(256) bias_kernel(
    const float* __restrict__ ab, const float* __restrict__ Wb,
    const float* __restrict__ bb, const float* __restrict__ seq_mask) {
  __shared__ float sWb[128];
  __shared__ float sbb[8];
  const int i = blockIdx.x;
  const int b = blockIdx.y;
  const int tid = threadIdx.x;
  if (tid < 128) sWb[tid] = Wb[tid];
  if (tid < 8) sbb[tid] = bb[tid];
  __syncthreads();
  const int j0 = tid << 2;
  float acc[8][4];
#pragma unroll
  for (int h = 0; h < 8; ++h) {
    float v = sbb[h];
    acc[h][0] = v; acc[h][1] = v; acc[h][2] = v; acc[h][3] = v;
  }
  const float* abp = ab + ((size_t)b * 16 * 1024 + i) * 1024 + j0;
#pragma unroll 4
  for (int a = 0; a < 16; ++a) {
    float4 v = *(const float4*)(abp + (size_t)a * 1024 * 1024);
#pragma unroll
    for (int h = 0; h < 8; ++h) {
      float w = sWb[h * 16 + a];
      acc[h][0] += w * v.x;
      acc[h][1] += w * v.y;
      acc[h][2] += w * v.z;
      acc[h][3] += w * v.w;
    }
  }
  const float mi = seq_mask[b * 1024 + i];
  float4 mj = *(const float4*)(seq_mask + b * 1024 + j0);
  const float p0 = -(1.f - mi * mj.x) * 1e6f;
  const float p1 = -(1.f - mi * mj.y) * 1e6f;
  const float p2 = -(1.f - mi * mj.z) * 1e6f;
  const float p3 = -(1.f - mi * mj.w) * 1e6f;
  bf16* outp = g_biasb + ((size_t)(b * 8) * 1024 + i) * 1024 + j0;
#pragma unroll
  for (int h = 0; h < 8; ++h) {
    __nv_bfloat162 o01 = __floats2bfloat162_rn(acc[h][0] + p0, acc[h][1] + p1);
    __nv_bfloat162 o23 = __floats2bfloat162_rn(acc[h][2] + p2, acc[h][3] + p3);
    bf16* op = outp + (size_t)h * 1024 * 1024;
    *(__nv_bfloat162*)op = o01;
    *(__nv_bfloat162*)(op + 2) = o23;
  }
}

// ---------------- FA2 attention: mma.sync + ldmatrix + cp.async -------------
// smem layout (bytes):
//   [0, 8192)        Qh   64x64 bf16 swizzled
//   [8192, 16384)    Ql
//   [16384 + s*ASTG) stage s: Kh(8192) Kl(8192) Vh(8192) Vl(8192) bias(9216)
#define ASTG 41984
#define ATTN_SMEM (16384 + 2 * ASTG)   // 100352

__device__ __forceinline__ void stage_tile(
    u32 base, const bf16* kh, const bf16* kl, const bf16* vh, const bf16* vl,
    const bf16* bg, int jt, int tid) {
#pragma unroll
  for (int it = 0; it < 4; ++it) {
    int idx = it * 128 + tid;
    int row = idx >> 3;
    int c = idx & 7;
    u32 off = (u32)(row * 128 + ((c ^ (row & 7)) << 4));
    size_t g = (size_t)jt * 4096 + row * 64 + c * 8;
    cp16(base + off, kh + g);
    cp16(base + 8192u + off, kl + g);
    cp16(base + 16384u + off, vh + g);
    cp16(base + 24576u + off, vl + g);
    cp16(base + 32768u + (u32)(row * 144 + (c << 4)),
         bg + (size_t)row * 1024 + jt * 64 + c * 8);
  }
}

__global__ void __launch_bounds__(128) attn_fa2() {
  extern __shared__ char smem_raw[];
  const u32 sb = (u32)__cvta_generic_to_shared(smem_raw);
  const int bh = blockIdx.y;
  const int itile = blockIdx.x;
  const int tid = threadIdx.x;
  const int wid = tid >> 5;
  const int lane = tid & 31;

  const bf16* qh = g_qh + (size_t)bh * 65536 + itile * 4096;
  const bf16* ql = g_ql + (size_t)bh * 65536 + itile * 4096;
  const bf16* kh = g_kh + (size_t)bh * 65536;
  const bf16* kl = g_kl + (size_t)bh * 65536;
  const bf16* vh = g_vh + (size_t)bh * 65536;
  const bf16* vl = g_vl + (size_t)bh * 65536;
  const bf16* bg = g_biasb + ((size_t)bh * 1024 + itile * 64) * 1024;

  // prologue: Q + tile 0 in one group
#pragma unroll
  for (int it = 0; it < 4; ++it) {
    int idx = it * 128 + tid;
    int row = idx >> 3;
    int c = idx & 7;
    u32 off = (u32)(row * 128 + ((c ^ (row & 7)) << 4));
    cp16(sb + off, qh + row * 64 + c * 8);
    cp16(sb + 8192u + off, ql + row * 64 + c * 8);
  }
  stage_tile(sb + 16384u, kh, kl, vh, vl, bg, 0, tid);
  cp_commit();

  float o[8][4];
#pragma unroll
  for (int nf = 0; nf < 8; ++nf) {
    o[nf][0] = 0.f; o[nf][1] = 0.f; o[nf][2] = 0.f; o[nf][3] = 0.f;
  }
  float m0 = -1e30f, m1 = -1e30f, l0 = 0.f, l1 = 0.f;
  const int qrow = wid * 16 + (lane >> 2);

  for (int jt = 0; jt < 16; ++jt) {
    const int buf = jt & 1;
    if (jt + 1 < 16) {
      stage_tile(sb + 16384u + (u32)((1 - buf) * ASTG), kh, kl, vh, vl, bg,
                 jt + 1, tid);
      cp_commit();
      cp_wait1();
    } else {
      cp_wait0();
    }
    __syncthreads();

    const u32 kbs = sb + 16384u + (u32)(buf * ASTG);
    const u32 klbs = kbs + 8192u;
    const u32 vbs = kbs + 16384u;
    const u32 vlbs = kbs + 24576u;
    const bf16* bs = (const bf16*)(smem_raw + 16384 + buf * ASTG + 32768);

    // ---- S = bias + Q K^T ----
    float s[8][4];
#pragma unroll
    for (int nf = 0; nf < 8; ++nf) {
      const bf16* bp = bs + qrow * 72 + nf * 8 + 2 * (lane & 3);
      float2 p0 = __bfloat1622float2(*(const __nv_bfloat162*)bp);
      float2 p1 = __bfloat1622float2(*(const __nv_bfloat162*)(bp + 8 * 72));
      s[nf][0] = p0.x; s[nf][1] = p0.y;
      s[nf][2] = p1.x; s[nf][3] = p1.y;
    }
#pragma unroll
    for (int ks = 0; ks < 4; ++ks) {
      u32 fah[4], fal[4];
      {
        int row = wid * 16 + (lane & 15);
        int ch = 2 * ks + (lane >> 4);
        u32 off = (u32)(row * 128 + ((ch ^ (row & 7)) << 4));
        ldm_x4(fah[0], fah[1], fah[2], fah[3], sb + off);
        ldm_x4(fal[0], fal[1], fal[2], fal[3], sb + 8192u + off);
      }
#pragma unroll
      for (int nf = 0; nf < 8; ++nf) {
        int row = nf * 8 + (lane & 7);
        int ch = 2 * ks + ((lane >> 3) & 1);
        u32 off = (u32)(row * 128 + ((ch ^ (row & 7)) << 4));
        u32 b0, b1, c0, c1;
        ldm_x2(b0, b1, kbs + off);
        ldm_x2(c0, c1, klbs + off);
        mma_bf(s[nf], fah, b0, b1);
        mma_bf(s[nf], fah, c0, c1);
        mma_bf(s[nf], fal, b0, b1);
      }
    }

    // ---- online softmax ----
    float mx0 = fmaxf(s[0][0], s[0][1]);
    float mx1 = fmaxf(s[0][2], s[0][3]);
#pragma unroll
    for (int nf = 1; nf < 8; ++nf) {
      mx0 = fmaxf(mx0, fmaxf(s[nf][0], s[nf][1]));
      mx1 = fmaxf(mx1, fmaxf(s[nf][2], s[nf][3]));
    }
    mx0 = fmaxf(mx0, __shfl_xor_sync(0xffffffffu, mx0, 1));
    mx0 = fmaxf(mx0, __shfl_xor_sync(0xffffffffu, mx0, 2));
    mx1 = fmaxf(mx1, __shfl_xor_sync(0xffffffffu, mx1, 1));
    mx1 = fmaxf(mx1, __shfl_xor_sync(0xffffffffu, mx1, 2));
    const float mn0 = fmaxf(m0, mx0);
    const float mn1 = fmaxf(m1, mx1);
    const float a0 = __expf(m0 - mn0);
    const float a1 = __expf(m1 - mn1);
    m0 = mn0;
    m1 = mn1;
    float sum0 = 0.f, sum1 = 0.f;
#pragma unroll
    for (int nf = 0; nf < 8; ++nf) {
      s[nf][0] = __expf(s[nf][0] - mn0);
      s[nf][1] = __expf(s[nf][1] - mn0);
      s[nf][2] = __expf(s[nf][2] - mn1);
      s[nf][3] = __expf(s[nf][3] - mn1);
      sum0 += s[nf][0] + s[nf][1];
      sum1 += s[nf][2] + s[nf][3];
    }
    sum0 += __shfl_xor_sync(0xffffffffu, sum0, 1);
    sum0 += __shfl_xor_sync(0xffffffffu, sum0, 2);
    sum1 += __shfl_xor_sync(0xffffffffu, sum1, 1);
    sum1 += __shfl_xor_sync(0xffffffffu, sum1, 2);
    l0 = l0 * a0 + sum0;
    l1 = l1 * a1 + sum1;
#pragma unroll
    for (int nf = 0; nf < 8; ++nf) {
      o[nf][0] *= a0;
      o[nf][1] *= a0;
      o[nf][2] *= a1;
      o[nf][3] *= a1;
    }

    // ---- O += P V ----
#pragma unroll
    for (int kf = 0; kf < 4; ++kf) {
      u32 ph[4], pl[4];
      pack_hl2(s[2 * kf][0], s[2 * kf][1], ph[0], pl[0]);
      pack_hl2(s[2 * kf][2], s[2 * kf][3], ph[1], pl[1]);
      pack_hl2(s[2 * kf + 1][0], s[2 * kf + 1][1], ph[2], pl[2]);
      pack_hl2(s[2 * kf + 1][2], s[2 * kf + 1][3], ph[3], pl[3]);
      {
        int row = kf * 16 + (lane & 15);
#pragma unroll
        for (int nf = 0; nf < 8; ++nf) {
          u32 off = (u32)(row * 128 + ((nf ^ (row & 7)) << 4));
          u32 b0, b1, c0, c1;
          ldm_x2t(b0, b1, vbs + off);
          ldm_x2t(c0, c1, vlbs + off);
          mma_bf(o[nf], ph, b0, b1);
          mma_bf(o[nf], ph, c0, c1);
          mma_bf(o[nf], pl, b0, b1);
        }
      }
    }
    __syncthreads();
  }

  // ---- epilogue ----
  const int b = bh >> 3;
  const int h = bh & 7;
  const float inv0 = 1.f / l0;
  const float inv1 = 1.f / l1;
  const int row0 = itile * 64 + qrow;
#pragma unroll
  for (int nf = 0; nf < 8; ++nf) {
    const int d0 = nf * 8 + 2 * (lane & 3);
    size_t idx = ((size_t)(b * 1024 + row0)) * 512 + h * 64 + d0;
    u32 hh, ll;
    pack_hl2(o[nf][0] * inv0, o[nf][1] * inv0, hh, ll);
    *(u32*)(g_oh + idx) = hh;
    *(u32*)(g_ol + idx) = ll;
    size_t idx1 = idx + 8 * 512;
    pack_hl2(o[nf][2] * inv1, o[nf][3] * inv1, hh, ll);
    *(u32*)(g_oh + idx1) = hh;
    *(u32*)(g_ol + idx1) = ll;
  }
}

// ---------------- launch ----------------------------------------------------
extern "C" void kernel_launch(void* const* d_in, const int* in_sizes, int n_in,
                              void* d_out, int out_size) {
  const float* x        = (const float*)d_in[0];
  const float* timep    = (const float*)d_in[1];
  const float* ab       = (const float*)d_in[2];
  const float* seq_mask = (const float*)d_in[3];
  const float* gamma    = (const float*)d_in[4];
  const float* Wt       = (const float*)d_in[5];
  const float* bt       = (const float*)d_in[6];
  const float* Wq       = (const float*)d_in[7];
  const float* Wkv      = (const float*)d_in[8];
  const float* Wo       = (const float*)d_in[9];
  const float* Wb       = (const float*)d_in[10];
  const float* bb       = (const float*)d_in[11];
  float* out = (float*)d_out;

  void *p_xh, *p_xl, *p_xnh, *p_xnl, *p_wqh, *p_wql, *p_wkvh, *p_wkvl;
  void *p_woh, *p_wol, *p_oh, *p_ol;
  cudaGetSymbolAddress(&p_xh, g_xh);
  cudaGetSymbolAddress(&p_xl, g_xl);
  cudaGetSymbolAddress(&p_xnh, g_xnh);
  cudaGetSymbolAddress(&p_xnl, g_xnl);
  cudaGetSymbolAddress(&p_wqh, g_wqh);
  cudaGetSymbolAddress(&p_wql, g_wql);
  cudaGetSymbolAddress(&p_wkvh, g_wkvh);
  cudaGetSymbolAddress(&p_wkvl, g_wkvl);
  cudaGetSymbolAddress(&p_woh, g_woh);
  cudaGetSymbolAddress(&p_wol, g_wol);
  cudaGetSymbolAddress(&p_oh, g_oh);
  cudaGetSymbolAddress(&p_ol, g_ol);

  cudaFuncSetAttribute(mma_gemm, cudaFuncAttributeMaxDynamicSharedMemorySize,
                       GEMM_SMEM);
  cudaFuncSetAttribute(attn_fa2, cudaFuncAttributeMaxDynamicSharedMemorySize,
                       ATTN_SMEM);

  convert_hl<<<2048, 256>>>(x, (bf16*)p_xh, (bf16*)p_xl);
  convert_hl<<<256, 256>>>(Wq, (bf16*)p_wqh, (bf16*)p_wql);
  convert_hl<<<512, 256>>>(Wkv, (bf16*)p_wkvh, (bf16*)p_wkvl);
  convert_hl<<<256, 256>>>(Wo, (bf16*)p_woh, (bf16*)p_wol);

  film_kernel<<<dim3(128, CB), 256>>>(timep, Wt, bt);
  ln_film_kernel<<<CB * CN, 128>>>(x, gamma, seq_mask);

  mma_gemm<<<dim3(4, 32), 256, GEMM_SMEM>>>(
      (const bf16*)p_xnh, (const bf16*)p_xnl,
      (const bf16*)p_wqh, (const bf16*)p_wql, nullptr, seq_mask, 0);
  mma_gemm<<<dim3(8, 32), 256, GEMM_SMEM>>>(
      (const bf16*)p_xh, (const bf16*)p_xl,
      (const bf16*)p_wkvh, (const bf16*)p_wkvl, nullptr, seq_mask, 1);

  bias_kernel<<<dim3(CN, CB), 256>>>(ab, Wb, bb, seq_mask);

  attn_fa2<<<dim3(16, 32), 128, ATTN_SMEM>>>();

  mma_gemm<<<dim3(4, 32), 256, GEMM_SMEM>>>(
      (const bf16*)p_oh, (const bf16*)p_ol,
      (const bf16*)p_woh, (const bf16*)p_wol, out, seq_mask, 2);
}